// round 14
// baseline (speedup 1.0000x reference)
#include <cuda_runtime.h>
#include <cuda_bf16.h>
#include <math.h>
#include <stdint.h>

#define B_ 32768
#define N_ 5
#define D_ 32
#define H_ 128
#define ROWS (B_*N_)          // 163840
#define BH (B_*H_)            // 4194304
#define SPLROW (ROWS*H_)

static constexpr long long OFF_VAR = (long long)B_*N_*D_;
static constexpr long long OFF_GRU = 2LL*B_*N_*D_;
static constexpr long long OFF_TOT = OFF_GRU + 2LL*B_*H_;
static constexpr long long OFF_LS  = OFF_TOT + 1;

// ---------------- static scratch ----------------
__device__ float BA[ROWS*H_];
__device__ float BB[ROWS*H_];
__device__ float BD[ROWS*H_];
__device__ float DEC[ROWS*64];
__device__ float GI[B_*384];
__device__ float GH[B_*384];
__device__ float ZB[512];

__device__ __nv_bfloat16 S0[2*SPLROW];
__device__ __nv_bfloat16 S1[2*SPLROW];
__device__ __nv_bfloat16 S2[2*SPLROW];
__device__ __nv_bfloat16 XS[2*B_*N_*D_];
__device__ __nv_bfloat16 HS[2*2*BH];
__device__ __nv_bfloat16 GFS[2*B_*H_];
__device__ __nv_bfloat16 CS[2*B_*H_];

// bf16 hi/lo weight images in 64-column chunks: chunk = [hi 64xKPR][lo 64xKPR]
static constexpr int CH136 = 2*64*136;
static constexpr int CH40  = 2*64*40;

static constexpr int IMG_ENC1 = 0;
static constexpr int IMG_ENC2 = IMG_ENC1 + 5*2*CH40;
static constexpr int IMG_GCN  = IMG_ENC2 + 5*2*CH136;
static constexpr int IMG_MU   = IMG_GCN  + 2*2*CH136;
static constexpr int IMG_SG   = IMG_MU   + 2*CH136;     // contiguous after MU (fused pass)
static constexpr int IMG_GRU  = IMG_SG   + 2*CH136;     // per l: [ih 6CH][hh 6CH]
static constexpr int IMG_CM1  = IMG_GRU  + 24*CH136;
static constexpr int IMG_CM2  = IMG_CM1  + 2*CH136;
static constexpr int IMG_DW1  = IMG_CM2  + 2*CH136;
static constexpr int IMG_DW2  = IMG_DW1  + 5*2*CH136;
static constexpr int IMG_END  = IMG_DW2  + 5*1*CH136;
__device__ __align__(256) __nv_bfloat16 WIMG[IMG_END];

// accumulators: 0 kl, 1 ll, 2 reg, 3 cls, 4 lz
__device__ double g_acc[8];
__device__ double g_piw[32], g_k[32];
__device__ unsigned g_mn[32], g_mx[32];

// ---------------- helpers ----------------
__device__ __forceinline__ float softplusf(float x){ return fmaxf(x,0.f)+log1pf(expf(-fabsf(x))); }
__device__ __forceinline__ float mishf(float x){ return x*tanhf(softplusf(x)); }
__device__ __forceinline__ float sigmf(float x){ return 1.f/(1.f+expf(-x)); }
__device__ __forceinline__ unsigned fenc(float f){ unsigned u=__float_as_uint(f); return (u&0x80000000u)?~u:(u|0x80000000u); }
__device__ __forceinline__ float fdec(unsigned u){ return (u&0x80000000u)?__uint_as_float(u&0x7fffffffu):__uint_as_float(~u); }

__device__ __forceinline__ uint32_t smem_u32(const void* p){
    uint32_t a;
    asm("{ .reg .u64 t; cvta.to.shared.u64 t, %1; cvt.u32.u64 %0, t; }" : "=r"(a) : "l"(p));
    return a;
}
__device__ __forceinline__ void bsplit(float x, unsigned short& h, unsigned short& l){
    __nv_bfloat16 hb = __float2bfloat16(x);
    __nv_bfloat16 lb = __float2bfloat16(x - __bfloat162float(hb));
    h = __bfloat16_as_ushort(hb);
    l = __bfloat16_as_ushort(lb);
}
__device__ __forceinline__ void spstore(__nv_bfloat16* hi, __nv_bfloat16* lo, size_t idx, float v){
    unsigned short h,l; bsplit(v,h,l);
    hi[idx]=__ushort_as_bfloat16(h); lo[idx]=__ushort_as_bfloat16(l);
}

#define LDM4(r, addr) \
    asm volatile("ldmatrix.sync.aligned.m8n8.x4.shared.b16 {%0,%1,%2,%3}, [%4];" \
        : "=r"((r)[0]), "=r"((r)[1]), "=r"((r)[2]), "=r"((r)[3]) : "r"(addr))

#define MMA16816(c, a, b0, b1) \
    asm volatile("mma.sync.aligned.m16n8k16.row.col.f32.bf16.bf16.f32 " \
        "{%0,%1,%2,%3},{%4,%5,%6,%7},{%8,%9},{%0,%1,%2,%3};" \
        : "+f"((c)[0]), "+f"((c)[1]), "+f"((c)[2]), "+f"((c)[3]) \
        : "r"((a)[0]), "r"((a)[1]), "r"((a)[2]), "r"((a)[3]), "r"(b0), "r"(b1))

__global__ void init_k(){
    int i=threadIdx.x;
    if(i<8) g_acc[i]=0.0;
    if(i<32){ g_piw[i]=0.0; g_k[i]=0.0; g_mn[i]=0xffffffffu; g_mx[i]=0u; }
    for (int j=i;j<512;j+=64) ZB[j]=0.f;
}

// ---------------- input splits ----------------
__global__ void xsplit_k(const float* __restrict__ x, __nv_bfloat16* __restrict__ XSp){
    int total = B_*N_*D_;
    for (int idx = blockIdx.x*blockDim.x + threadIdx.x; idx < total; idx += gridDim.x*blockDim.x){
        int b = idx/160, rem = idx - b*160;
        int z = rem>>5, k = rem&31;
        size_t o = (size_t)z*B_*32 + b*32 + k;
        spstore(XSp, XSp + (size_t)N_*B_*32, o, x[idx]);
    }
}
__global__ void hsplit_k(const float* __restrict__ hist, __nv_bfloat16* __restrict__ HSp){
    int total = 2*BH;
    for (int idx = blockIdx.x*blockDim.x + threadIdx.x; idx < total; idx += gridDim.x*blockDim.x){
        int l = idx/BH, rem = idx - l*BH;
        spstore(HSp + (size_t)l*2*BH, HSp + (size_t)l*2*BH + BH, rem, hist[idx]);
    }
}

// ---------------- merged weight prep ----------------
struct PrepD {
    const float* W;
    int ldw, wstride, Kreal, NB, KPR, zc, nk;
    long long imgoff;
};
struct PrepAll { PrepD d[13]; };

__global__ void prep_all_k(PrepAll pa, __nv_bfloat16* __restrict__ img){
    const PrepD d = pa.d[blockIdx.x];
    int per = d.NB*d.Kreal;
    int total = d.zc*per;
    int nch = d.NB>>6;
    for (int i = blockIdx.y*blockDim.x + threadIdx.x; i < total; i += gridDim.y*blockDim.x){
        int z2 = i/per, rem = i - z2*per;
        int k,n;
        if (d.nk){ n = rem/d.Kreal; k = rem - n*d.Kreal; }
        else     { k = rem/d.NB;    n = rem - k*d.NB; }
        float v = d.W[(size_t)z2*d.wstride + (d.nk ? (size_t)n*d.ldw + k : (size_t)k*d.ldw + n)];
        unsigned short h,l; bsplit(v,h,l);
        int ch = n>>6, nl = n&63;
        size_t off = (size_t)d.imgoff + ((size_t)z2*nch + ch)*(2*64*d.KPR) + (size_t)nl*d.KPR + k;
        img[off] = __ushort_as_bfloat16(h);
        img[off + 64*d.KPR] = __ushort_as_bfloat16(l);
    }
}

// ---------------- bf16x3 GEMM: A resident in smem, loop over 64-col B chunks ----------------
#define EPI_NONE 0
#define EPI_RELU 1
#define EPI_MISH 2
#define EPI_SIGKL 3
#define EPI_LZ 4
#define EPI_MUSIG 5

template<int KK, int EPI, int OS>
__global__ __launch_bounds__(256)
void gemm_mm(const __nv_bfloat16* __restrict__ Ah, int lda, long long azs, int asplen,
             const __nv_bfloat16* __restrict__ img, int nch,
             const float* __restrict__ bias, int biaszs,
             const float* __restrict__ bias2,
             void* __restrict__ Cv, int ldc, long long czs, int csplen,
             const float* __restrict__ aux, int aldc)
{
    constexpr int KPR = KK + 8;
    constexpr int APL = 128*KPR*2;
    constexpr int BPL = 64*KPR*2;
    constexpr int MT = 2;

    extern __shared__ __align__(16) char smem[];
    char* sAh = smem;
    char* sBh = smem + 2*APL;
    double* red = (double*)(smem + 2*APL + 2*BPL);

    int tid = threadIdx.x, wid = tid>>5, lane = tid&31;
    int z = blockIdx.z;
    bias += (size_t)z*biaszs;
    int row0 = blockIdx.y*128;

    float* Cf = nullptr; __nv_bfloat16* Csp = nullptr;
    if (OS==0 && (EPI<EPI_SIGKL || EPI==EPI_MUSIG)) Cf = (float*)Cv + (long long)z*czs;
    if (OS==1) Csp = (__nv_bfloat16*)Cv + (long long)z*czs;

    // ---- copy A tile (pre-split) once ----
    {
        const __nv_bfloat16* Abase = Ah + (long long)z*azs + (size_t)row0*lda;
        constexpr int CHk = KK/8;
        constexpr int TOT = 128*CHk*2;
        #pragma unroll
        for (int i=0;i<TOT/256;i++){
            int idx=i*256+tid;
            int p = idx/(128*CHk); int rem = idx - p*(128*CHk);
            int row = rem/CHk, ck = rem - row*CHk;
            uint4 v = *reinterpret_cast<const uint4*>(Abase + (size_t)p*asplen + (size_t)row*lda + ck*8);
            *reinterpret_cast<uint4*>(sAh + (size_t)p*APL + row*KPR*2 + ck*16) = v;
        }
    }

    int wm = wid & 3, wn = wid >> 2;
    int m_base = wm*32, n_base = wn*32;
    int lr = lane & 15, lc = lane >> 4;
    int rsel = lane>>2, csel = (lane&3)*2;

    uint32_t abase = smem_u32(sAh);
    uint32_t bbase = smem_u32(sBh);
    uint32_t arow[MT], brow[2];
    #pragma unroll
    for (int mt=0; mt<MT; mt++) arow[mt] = abase + ((m_base + mt*16 + lr)*KPR)*2 + lc*16;
    #pragma unroll
    for (int g=0; g<2; g++)     brow[g] = bbase + ((n_base + g*16 + lr)*KPR)*2 + lc*16;

    double part = 0.0;

    for (int ch=0; ch<nch; ch++){
        __syncthreads();
        {
            const float4* src = reinterpret_cast<const float4*>(img + ((size_t)z*nch + ch)*(2*64*KPR));
            float4* dst = reinterpret_cast<float4*>(sBh);
            constexpr int CNT = 2*BPL/16;
            for (int i=tid; i<CNT; i+=256) dst[i] = src[i];
        }
        __syncthreads();

        float c[MT][4][4];
        #pragma unroll
        for(int mt=0;mt<MT;mt++)
            #pragma unroll
            for(int nt=0;nt<4;nt++)
                #pragma unroll
                for(int q=0;q<4;q++) c[mt][nt][q]=0.f;

        for (int ks=0; ks<KK/16; ks++){
            uint32_t koff = ks*32;
            uint32_t ah[MT][4], al[MT][4];
            #pragma unroll
            for (int mt=0; mt<MT; mt++){
                LDM4(ah[mt], arow[mt] + koff);
                LDM4(al[mt], arow[mt] + koff + APL);
            }
            uint32_t bh0[4],bh1[4],bl0[4],bl1[4];
            #pragma unroll
            for (int g=0; g<2; g++){
                uint32_t r[4];
                LDM4(r, brow[g] + koff);
                bh0[2*g]=r[0]; bh0[2*g+1]=r[1]; bh1[2*g]=r[2]; bh1[2*g+1]=r[3];
                LDM4(r, brow[g] + koff + BPL);
                bl0[2*g]=r[0]; bl0[2*g+1]=r[1]; bl1[2*g]=r[2]; bl1[2*g+1]=r[3];
            }
            #pragma unroll
            for (int mt=0; mt<MT; mt++){
                #pragma unroll
                for (int nt=0; nt<4; nt++){
                    MMA16816(c[mt][nt], ah[mt], bh0[nt], bh1[nt]);
                    MMA16816(c[mt][nt], ah[mt], bl0[nt], bl1[nt]);
                    MMA16816(c[mt][nt], al[mt], bh0[nt], bh1[nt]);
                }
            }
        }

        // ---- per-chunk epilogue ----
        int col0 = ch*64;
        int musig_sig = (EPI==EPI_MUSIG) && (ch>=2);
        #pragma unroll
        for (int mt=0; mt<MT; mt++){
            int rloc = m_base + mt*16 + rsel;
            #pragma unroll
            for (int nt=0; nt<4; nt++){
                int cg = col0 + n_base + nt*8 + csel;
                float b0, b1;
                if (EPI==EPI_MUSIG && musig_sig){ b0 = bias2[cg-128]; b1 = bias2[cg-127]; }
                else { b0 = bias[cg]; b1 = bias[cg+1]; }
                #pragma unroll
                for (int half=0; half<2; half++){
                    int row = row0 + rloc + half*8;
                    float v0 = c[mt][nt][half*2+0] + b0;
                    float v1 = c[mt][nt][half*2+1] + b1;
                    if (EPI==EPI_SIGKL || EPI==EPI_LZ){
                        const float* ap = &aux[(size_t)row*aldc + cg];
                        float m0 = ap[0], m1 = ap[1];
                        if (EPI==EPI_SIGKL){
                            float sp0 = softplusf(v0), sp1 = softplusf(v1);
                            float va0 = sp0*sp0, va1 = sp1*sp1;
                            part += (double)(0.5f*(m0*m0 + va0 - logf(va0+1e-8f) - 1.0f));
                            part += (double)(0.5f*(m1*m1 + va1 - logf(va1+1e-8f) - 1.0f));
                        } else {
                            float d0 = m0-v0, d1 = m1-v1;
                            part += (double)(d0*d0) + (double)(d1*d1);
                        }
                    } else if (EPI==EPI_MUSIG){
                        if (!musig_sig){
                            float2 ov; ov.x=v0; ov.y=v1;
                            *reinterpret_cast<float2*>(&Cf[(size_t)row*ldc + cg]) = ov;
                        } else {
                            // same thread wrote these mean values in chunk ch-2 (program order)
                            const float* mp = &Cf[(size_t)row*ldc + (cg-128)];
                            float m0 = mp[0], m1 = mp[1];
                            float sp0 = softplusf(v0), sp1 = softplusf(v1);
                            float va0 = sp0*sp0, va1 = sp1*sp1;
                            part += (double)(0.5f*(m0*m0 + va0 - logf(va0+1e-8f) - 1.0f));
                            part += (double)(0.5f*(m1*m1 + va1 - logf(va1+1e-8f) - 1.0f));
                        }
                    } else {
                        if (EPI==EPI_RELU){ v0=fmaxf(v0,0.f); v1=fmaxf(v1,0.f); }
                        else if (EPI==EPI_MISH){ v0=mishf(v0); v1=mishf(v1); }
                        size_t o = (size_t)row*ldc + cg;
                        if (OS==0){
                            float2 ov; ov.x=v0; ov.y=v1;
                            *reinterpret_cast<float2*>(&Cf[o]) = ov;
                        } else {
                            unsigned short h0,l0,h1,l1; bsplit(v0,h0,l0); bsplit(v1,h1,l1);
                            *reinterpret_cast<uint32_t*>(&Csp[o]) = (unsigned)h0 | ((unsigned)h1<<16);
                            *reinterpret_cast<uint32_t*>(&Csp[o+csplen]) = (unsigned)l0 | ((unsigned)l1<<16);
                        }
                    }
                }
            }
        }
    }

    if (EPI==EPI_SIGKL || EPI==EPI_LZ || EPI==EPI_MUSIG){
        #pragma unroll
        for (int o=16;o;o>>=1) part += __shfl_xor_sync(0xffffffffu, part, o);
        __syncthreads();
        if (lane==0) red[wid]=part;
        __syncthreads();
        if (tid==0){
            double s=0; for(int w=0;w<8;w++) s+=red[w];
            atomicAdd(&g_acc[EPI==EPI_LZ?4:0], s);
        }
    }
}

// ---------------- elementwise kernels ----------------
__global__ void agg_k(const float* __restrict__ g, const float* __restrict__ ew,
                      __nv_bfloat16* __restrict__ S){
    int idx = blockIdx.x*256+threadIdx.x;
    int b=idx>>7, h=idx&127;
    const float* gb = g + (size_t)b*640 + h;
    float g0=gb[0],g1=gb[128],g2=gb[256],g3=gb[384],g4=gb[512];
    const float* e = ew + (size_t)b*10;
    float o0 = g0;
    float o1 = g1 + e[0]*g0;
    float o2 = g2 + e[1]*g0 + e[4]*g1;
    float o3 = g3 + e[2]*g0 + e[5]*g1 + e[7]*g2;
    float o4 = g4 + e[3]*g0 + e[6]*g1 + e[8]*g2 + e[9]*g3;
    __nv_bfloat16* lo = S + SPLROW;
    size_t base = (size_t)b*640 + h;
    spstore(S,lo,base,      o0);
    spstore(S,lo,base+128,  o1);
    spstore(S,lo,base+256,  o2);
    spstore(S,lo,base+384,  o3);
    spstore(S,lo,base+512,  o4);
}

__global__ void gf_k(const float* __restrict__ m, __nv_bfloat16* __restrict__ G){
    int idx = blockIdx.x*256+threadIdx.x;
    int b=idx>>7, h=idx&127;
    const float* mb = m + (size_t)b*640 + h;
    spstore(G, G + (size_t)B_*H_, idx, (mb[0]+mb[128]+mb[256]+mb[384]+mb[512])*0.2f);
}

__global__ void cell_k(const float* __restrict__ gi, const float* __restrict__ gh,
                       const float* __restrict__ bih, const float* __restrict__ bhh,
                       const float* __restrict__ hprev, float* __restrict__ hout,
                       __nv_bfloat16* __restrict__ cs){
    int idx = blockIdx.x*256+threadIdx.x;
    int b=idx>>7, h=idx&127;
    int base = b*384 + h;
    float r = sigmf(gi[base]     + bih[h]     + gh[base]     + bhh[h]);
    float z = sigmf(gi[base+128] + bih[128+h] + gh[base+128] + bhh[128+h]);
    float n = tanhf(gi[base+256] + bih[256+h] + r*(gh[base+256] + bhh[256+h]));
    float v = (1.f-z)*n + z*hprev[idx];
    hout[idx] = v;
    if (cs) spstore(cs, cs + (size_t)B_*H_, idx, v);
}

__global__ void causal_k(const float* __restrict__ m, const float* __restrict__ ew,
                         const float* __restrict__ cm, float* __restrict__ czf,
                         __nv_bfloat16* __restrict__ CZ, __nv_bfloat16* __restrict__ PS){
    int idx = blockIdx.x*256+threadIdx.x;
    int b=idx>>7, h=idx&127;
    const float* mb = m + (size_t)b*640 + h;
    const float* e  = ew + (size_t)b*10;
    float c01=cm[1]*e[0],  c02=cm[2]*e[1],  c03=cm[3]*e[2],  c04=cm[4]*e[3];
    float c12=cm[7]*e[4],  c13=cm[8]*e[5],  c14=cm[9]*e[6];
    float c23=cm[13]*e[7], c24=cm[14]*e[8];
    float c34=cm[19]*e[9];
    float z0=mb[0];
    float z1=mb[128]+c01*z0;
    float z2=mb[256]+c02*z0+c12*z1;
    float z3=mb[384]+c03*z0+c13*z1+c23*z2;
    float z4=mb[512]+c04*z0+c14*z1+c24*z2+c34*z3;
    size_t base = (size_t)b*640 + h;
    float* czb = czf + base;
    czb[0]=z0; czb[128]=z1; czb[256]=z2; czb[384]=z3; czb[512]=z4;
    __nv_bfloat16* czlo = CZ + SPLROW;
    spstore(CZ,czlo,base,z0); spstore(CZ,czlo,base+128,z1); spstore(CZ,czlo,base+256,z2);
    spstore(CZ,czlo,base+384,z3); spstore(CZ,czlo,base+512,z4);
    float zv[5]={z0,z1,z2,z3,z4};
    __nv_bfloat16* pslo = PS + SPLROW;
    #pragma unroll
    for(int j=0;j<5;j++){
        float s=0.f;
        #pragma unroll
        for(int i=0;i<5;i++){
            if (cm[i*5+j]!=0.f) s += zv[i];
        }
        spstore(PS,pslo,base + (size_t)j*128, s);
    }
}

__global__ __launch_bounds__(256)
void loss_k(const float* __restrict__ dec, const float* __restrict__ ytp, float* __restrict__ out){
    int warp = threadIdx.x>>5, lane = threadIdx.x&31;
    int base = blockIdx.x*128;
    const float ZA = 1.959963984540054f;
    double ll_s=0.0, piw_s=0.0;
    float reg_s=0.f, cls_s=0.f;
    int k_s=0;
    float mn=3e38f, mx=-3e38f;
    for(int t=0;t<16;t++){
        int row = base + warp*16 + t;
        int n = row % 5;
        const float* dr = dec + (size_t)row*64;
        float mean = dr[lane];
        float var  = expf(dr[32+lane]);
        size_t oi = (size_t)row*32 + lane;
        out[oi]=mean; out[OFF_VAR+oi]=var;
        float yt = ytp[oi];
        float vs = var+1e-6f;
        float dm = yt-mean;
        ll_s += (double)(-0.5f*(dm*dm/vs + logf(6.283185307179586f*vs)));
        float d2 = dm*dm;
        float ssum=d2;
        #pragma unroll
        for(int o=16;o;o>>=1) ssum += __shfl_xor_sync(0xffffffffu,ssum,o);
        if (lane==0 && n<4) reg_s += ssum*(1.f/32.f);
        if (n==4){
            float bce = fmaxf(mean,0.f)-mean*yt+log1pf(expf(-fabsf(mean)));
            float bs=bce;
            #pragma unroll
            for(int o=16;o;o>>=1) bs += __shfl_xor_sync(0xffffffffu,bs,o);
            if (lane==0) cls_s += bs*(1.f/32.f);
        }
        float s = sqrtf(var+1e-6f);
        float lo = mean-ZA*s, up = mean+ZA*s;
        if (yt>=lo && yt<=up){ piw_s += (double)(up-lo); k_s++; }
        mn=fminf(mn,yt); mx=fmaxf(mx,yt);
    }
    #pragma unroll
    for(int o=16;o;o>>=1) ll_s += __shfl_xor_sync(0xffffffffu,ll_s,o);

    __shared__ double sll[8];
    __shared__ float sreg[8], scls[8];
    __shared__ float spiw[8][32], sk[8][32];
    __shared__ unsigned smn[8][32], smx[8][32];
    if (lane==0){ sll[warp]=ll_s; sreg[warp]=reg_s; scls[warp]=cls_s; }
    spiw[warp][lane]=(float)piw_s; sk[warp][lane]=(float)k_s;
    smn[warp][lane]=fenc(mn); smx[warp][lane]=fenc(mx);
    __syncthreads();
    if (warp==0){
        double psum=0, ksum=0; unsigned mnu=0xffffffffu, mxu=0u;
        for(int w=0;w<8;w++){
            psum+=(double)spiw[w][lane]; ksum+=(double)sk[w][lane];
            mnu=min(mnu,smn[w][lane]); mxu=max(mxu,smx[w][lane]);
        }
        atomicAdd(&g_piw[lane],psum); atomicAdd(&g_k[lane],ksum);
        atomicMin(&g_mn[lane],mnu);   atomicMax(&g_mx[lane],mxu);
        if (lane==0){
            double L=0; float R=0,Cc=0;
            for(int w=0;w<8;w++){ L+=sll[w]; R+=sreg[w]; Cc+=scls[w]; }
            atomicAdd(&g_acc[1],L); atomicAdd(&g_acc[2],(double)R); atomicAdd(&g_acc[3],(double)Cc);
        }
    }
}

__global__ void fin_k(float* __restrict__ out){
    int lane=threadIdx.x;
    double t=0.0, kc=0.0;
    double p=g_piw[lane]; kc=g_k[lane];
    float ymn=fdec(g_mn[lane]), ymx=fdec(g_mx[lane]);
    t = p/(kc+1e-6)/((double)(ymx-ymn)+1e-6);
    #pragma unroll
    for(int o=16;o;o>>=1){
        t  += __shfl_xor_sync(0xffffffffu,t,o);
        kc += __shfl_xor_sync(0xffffffffu,kc,o);
    }
    if (lane==0){
        float pinaw=(float)(t/32.0);
        float picp =(float)(kc/5242880.0);
        float kl   =(float)g_acc[0];
        float elbo = kl/32768.0f - (float)(g_acc[1]/5242880.0);
        float l_reg=(float)(g_acc[2]/(4.0*32768.0+1e-6));
        float l_cls=(float)(g_acc[3]/(32768.0+1e-6));
        float l_rec=l_reg+l_cls;
        float l_pi = pinaw - sqrtf(5.f)*picp;
        float l_z  =(float)(g_acc[4]/(163840.0*128.0));
        float dag  = 0.f;  // trace((I+ac)^5) == N exactly (strictly upper triangular)
        float total= powf(elbo*l_rec*l_pi*l_z*(dag+1e-6f), 0.2f);
        out[OFF_TOT]=total;
        out[OFF_LS+0]=elbo; out[OFF_LS+1]=l_rec; out[OFF_LS+2]=l_pi;
        out[OFF_LS+3]=l_z;  out[OFF_LS+4]=dag;
    }
}

// ---------------- launcher ----------------
static inline int smsz(int KK){
    int KPR = KK+8;
    return 2*(128*KPR*2) + 2*(64*KPR*2) + 64;
}

extern "C" void kernel_launch(void* const* d_in, const int* in_sizes, int n_in,
                              void* d_out, int out_size)
{
    const float* x    =(const float*)d_in[0];
    const float* ytr  =(const float*)d_in[1];
    const float* ew   =(const float*)d_in[2];
    const float* hist =(const float*)d_in[3];
    const float* eW1  =(const float*)d_in[4];
    const float* eb1  =(const float*)d_in[5];
    const float* eW2  =(const float*)d_in[6];
    const float* eb2  =(const float*)d_in[7];
    const float* gW   =(const float*)d_in[8];
    const float* gb   =(const float*)d_in[9];
    const float* muW  =(const float*)d_in[10];
    const float* mub  =(const float*)d_in[11];
    const float* sgW  =(const float*)d_in[12];
    const float* sgb  =(const float*)d_in[13];
    const float* Wih  =(const float*)d_in[14];
    const float* Whh  =(const float*)d_in[15];
    const float* bih  =(const float*)d_in[16];
    const float* bhh  =(const float*)d_in[17];
    const float* cm   =(const float*)d_in[18];
    const float* cW1  =(const float*)d_in[19];
    const float* cb1  =(const float*)d_in[20];
    const float* cW2  =(const float*)d_in[21];
    const float* cb2  =(const float*)d_in[22];
    const float* dW1  =(const float*)d_in[23];
    const float* db1  =(const float*)d_in[24];
    const float* dW2  =(const float*)d_in[25];
    const float* db2  =(const float*)d_in[26];
    float* out=(float*)d_out;

    float *pBA,*pBB,*pBD,*pDEC,*pGI,*pGH,*pZB;
    __nv_bfloat16 *pW,*pS0,*pS1,*pS2,*pXS,*pHS,*pGFS,*pCS;
    cudaGetSymbolAddress((void**)&pBA,BA);
    cudaGetSymbolAddress((void**)&pBB,BB);
    cudaGetSymbolAddress((void**)&pBD,BD);
    cudaGetSymbolAddress((void**)&pDEC,DEC);
    cudaGetSymbolAddress((void**)&pGI,GI);
    cudaGetSymbolAddress((void**)&pGH,GH);
    cudaGetSymbolAddress((void**)&pZB,ZB);
    cudaGetSymbolAddress((void**)&pW,WIMG);
    cudaGetSymbolAddress((void**)&pS0,S0);
    cudaGetSymbolAddress((void**)&pS1,S1);
    cudaGetSymbolAddress((void**)&pS2,S2);
    cudaGetSymbolAddress((void**)&pXS,XS);
    cudaGetSymbolAddress((void**)&pHS,HS);
    cudaGetSymbolAddress((void**)&pGFS,GFS);
    cudaGetSymbolAddress((void**)&pCS,CS);

    const int SM_MAIN = smsz(128);
    const int SM_ENC1 = smsz(32);
    cudaFuncSetAttribute(gemm_mm<128,EPI_NONE,0>,  cudaFuncAttributeMaxDynamicSharedMemorySize, SM_MAIN);
    cudaFuncSetAttribute(gemm_mm<128,EPI_RELU,0>,  cudaFuncAttributeMaxDynamicSharedMemorySize, SM_MAIN);
    cudaFuncSetAttribute(gemm_mm<128,EPI_RELU,1>,  cudaFuncAttributeMaxDynamicSharedMemorySize, SM_MAIN);
    cudaFuncSetAttribute(gemm_mm<128,EPI_MISH,1>,  cudaFuncAttributeMaxDynamicSharedMemorySize, SM_MAIN);
    cudaFuncSetAttribute(gemm_mm<128,EPI_MUSIG,0>, cudaFuncAttributeMaxDynamicSharedMemorySize, SM_MAIN);
    cudaFuncSetAttribute(gemm_mm<128,EPI_LZ,0>,    cudaFuncAttributeMaxDynamicSharedMemorySize, SM_MAIN);
    cudaFuncSetAttribute(gemm_mm<32,EPI_RELU,1>,   cudaFuncAttributeMaxDynamicSharedMemorySize, SM_ENC1);

    // merged prep descriptor table
    PrepAll pa;
    auto setd=[&](int i, const float* W, int ldw, int ws, int Kr, int NB, int KPR, int zc, int nk, long long off){
        pa.d[i] = PrepD{W,ldw,ws,Kr,NB,KPR,zc,nk,off};
    };
    setd(0,  eW1, 128, 4096,  32, 128, 40, 5, 0, IMG_ENC1);
    setd(1,  eW2, 128, 16384, 128,128,136, 5, 0, IMG_ENC2);
    setd(2,  gW,  128, 16384, 128,128,136, 2, 0, IMG_GCN);
    setd(3,  muW, 128, 0,     128,128,136, 1, 0, IMG_MU);
    setd(4,  sgW, 128, 0,     128,128,136, 1, 0, IMG_SG);
    setd(5,  Wih,        128, 16384, 128,128,136, 3, 1, IMG_GRU);
    setd(6,  Whh,        128, 16384, 128,128,136, 3, 1, IMG_GRU+6LL*CH136);
    setd(7,  Wih+49152,  128, 16384, 128,128,136, 3, 1, IMG_GRU+12LL*CH136);
    setd(8,  Whh+49152,  128, 16384, 128,128,136, 3, 1, IMG_GRU+18LL*CH136);
    setd(9,  cW1, 128, 0,     128,128,136, 1, 0, IMG_CM1);
    setd(10, cW2, 128, 0,     128,128,136, 1, 0, IMG_CM2);
    setd(11, dW1, 128, 16384, 128,128,136, 5, 0, IMG_DW1);
    setd(12, dW2, 64,  8192,  128, 64,136, 5, 0, IMG_DW2);

    // order: enc2 GEMM at graph node ~5 for ncu capture
    init_k<<<1,64>>>();                                 // 0
    xsplit_k<<<1024,256>>>(x, pXS);                     // 1
    hsplit_k<<<2048,256>>>(hist, pHS);                  // 2
    prep_all_k<<<dim3(13,24),256>>>(pa, pW);            // 3
    gemm_mm<32,EPI_RELU,1><<<dim3(1,256,5),256,SM_ENC1>>>(      // 4: enc1
        pXS,32,B_*32,N_*B_*32, pW+IMG_ENC1,2, eb1,128, nullptr, pS0,128,B_*128,SPLROW, nullptr,0);
    gemm_mm<128,EPI_NONE,0><<<dim3(1,256,5),256,SM_MAIN>>>(     // 5: enc2
        pS0,128,B_*128,SPLROW, pW+IMG_ENC2,2, eb2,128, nullptr, pBB,640,128,0, nullptr,0);

    // ---- GCN x2 ----
    agg_k<<<16384,256>>>(pBB, ew, pS1);
    gemm_mm<128,EPI_RELU,0><<<dim3(1,1280,1),256,SM_MAIN>>>(
        pS1,128,0,SPLROW, pW+IMG_GCN,2,         gb,0, nullptr, pBA,128,0,0, nullptr,0);
    agg_k<<<16384,256>>>(pBA, ew, pS0);
    gemm_mm<128,EPI_RELU,1><<<dim3(1,1280,1),256,SM_MAIN>>>(
        pS0,128,0,SPLROW, pW+IMG_GCN+2*CH136,2, gb+128,0, nullptr, pS1,128,0,SPLROW, nullptr,0);

    // ---- mu+sigma fused (+KL) ----
    gemm_mm<128,EPI_MUSIG,0><<<dim3(1,1280,1),256,SM_MAIN>>>(
        pS1,128,0,SPLROW, pW+IMG_MU,4, mub,0, sgb, pBD,128,0,0, nullptr,0);

    gf_k<<<16384,256>>>(pBD, pGFS);

    // ---- GRU x2 (ih+hh merged per layer via grid.z) ----
    const __nv_bfloat16* ginS = pGFS;
    for (int l=0;l<2;l++){
        const __nv_bfloat16* hS = pHS + (size_t)l*2*BH;
        long long azs = (long long)(hS - ginS);
        long long czs = (long long)(pGH - pGI);
        gemm_mm<128,EPI_NONE,0><<<dim3(1,256,2),256,SM_MAIN>>>(
            ginS,128,azs,B_*128, pW+IMG_GRU+(size_t)l*12*CH136,6, pZB,0, nullptr, pGI,384,czs,0, nullptr,0);
        cell_k<<<16384,256>>>(pGI,pGH, bih+l*384, bhh+l*384, hist+(size_t)l*BH,
                              out+OFF_GRU+(size_t)l*BH, l==0 ? pCS : (__nv_bfloat16*)nullptr);
        ginS = pCS;
    }

    // ---- causal + cm MLP(+l_z) ----
    causal_k<<<16384,256>>>(pBD, ew, cm, pBA, pS0, pS1);
    gemm_mm<128,EPI_MISH,1><<<dim3(1,1280,1),256,SM_MAIN>>>(
        pS1,128,0,SPLROW, pW+IMG_CM1,2, cb1,0, nullptr, pS2,128,0,SPLROW, nullptr,0);
    gemm_mm<128,EPI_LZ,0><<<dim3(1,1280,1),256,SM_MAIN>>>(
        pS2,128,0,SPLROW, pW+IMG_CM2,2, cb2,0, nullptr, nullptr,0,0,0, pBA,128);

    // ---- decoder ----
    gemm_mm<128,EPI_MISH,1><<<dim3(1,256,5),256,SM_MAIN>>>(
        pS0,640,128,SPLROW, pW+IMG_DW1,2, db1,128, nullptr, pS1,128,B_*128,SPLROW, nullptr,0);
    gemm_mm<128,EPI_NONE,0><<<dim3(1,256,5),256,SM_MAIN>>>(
        pS1,128,B_*128,SPLROW, pW+IMG_DW2,1, db2,64, nullptr, pDEC,320,64,0, nullptr,0);

    // ---- losses ----
    loss_k<<<1280,256>>>(pDEC, ytr, out);
    fin_k<<<1,32>>>(out);
}

// round 15
// speedup vs baseline: 1.3680x; 1.3680x over previous
#include <cuda_runtime.h>
#include <cuda_bf16.h>
#include <math.h>
#include <stdint.h>

#define B_ 32768
#define N_ 5
#define D_ 32
#define H_ 128
#define ROWS (B_*N_)          // 163840
#define BH (B_*H_)            // 4194304
#define SPLROW (ROWS*H_)      // split plane length for row-major activation mats

static constexpr long long OFF_VAR = (long long)B_*N_*D_;
static constexpr long long OFF_GRU = 2LL*B_*N_*D_;
static constexpr long long OFF_TOT = OFF_GRU + 2LL*B_*H_;
static constexpr long long OFF_LS  = OFF_TOT + 1;

// ---------------- static scratch ----------------
__device__ float BA[ROWS*H_];
__device__ float BB[ROWS*H_];
__device__ float BD[ROWS*H_];
__device__ float DEC[ROWS*64];
__device__ float GI[B_*384];
__device__ float GH[B_*384];

// bf16 hi/lo activation split buffers (hi plane then lo plane)
__device__ __nv_bfloat16 S0[2*SPLROW];
__device__ __nv_bfloat16 S1[2*SPLROW];
__device__ __nv_bfloat16 S2[2*SPLROW];
__device__ __nv_bfloat16 XS[2*B_*N_*D_];
__device__ __nv_bfloat16 HS[2*2*BH];
__device__ __nv_bfloat16 GFS[2*B_*H_];
__device__ __nv_bfloat16 CS[2*B_*H_];

// bf16 hi/lo weight images in 64-column chunks: chunk = [hi 64xKPR][lo 64xKPR]
static constexpr int CH136 = 2*64*136;
static constexpr int CH40  = 2*64*40;

static constexpr int IMG_ENC1 = 0;
static constexpr int IMG_ENC2 = IMG_ENC1 + 5*2*CH40;
static constexpr int IMG_GCN  = IMG_ENC2 + 5*2*CH136;
static constexpr int IMG_MU   = IMG_GCN  + 2*2*CH136;
static constexpr int IMG_SG   = IMG_MU   + 2*CH136;
static constexpr int IMG_WIH  = IMG_SG   + 2*CH136;
static constexpr int IMG_WHH  = IMG_WIH  + 12*CH136;
static constexpr int IMG_CM1  = IMG_WHH  + 12*CH136;
static constexpr int IMG_CM2  = IMG_CM1  + 2*CH136;
static constexpr int IMG_DW1  = IMG_CM2  + 2*CH136;
static constexpr int IMG_DW2  = IMG_DW1  + 5*2*CH136;
static constexpr int IMG_END  = IMG_DW2  + 5*1*CH136;
__device__ __align__(256) __nv_bfloat16 WIMG[IMG_END];

// accumulators: 0 kl, 1 ll, 2 reg, 3 cls, 4 lz
__device__ double g_acc[8];
__device__ double g_piw[32], g_k[32];
__device__ unsigned g_mn[32], g_mx[32];

// ---------------- helpers ----------------
__device__ __forceinline__ float softplusf(float x){ return fmaxf(x,0.f)+log1pf(expf(-fabsf(x))); }
__device__ __forceinline__ float mishf(float x){ return x*tanhf(softplusf(x)); }
__device__ __forceinline__ float sigmf(float x){ return 1.f/(1.f+expf(-x)); }
__device__ __forceinline__ unsigned fenc(float f){ unsigned u=__float_as_uint(f); return (u&0x80000000u)?~u:(u|0x80000000u); }
__device__ __forceinline__ float fdec(unsigned u){ return (u&0x80000000u)?__uint_as_float(u&0x7fffffffu):__uint_as_float(~u); }

__device__ __forceinline__ uint32_t smem_u32(const void* p){
    uint32_t a;
    asm("{ .reg .u64 t; cvta.to.shared.u64 t, %1; cvt.u32.u64 %0, t; }" : "=r"(a) : "l"(p));
    return a;
}
__device__ __forceinline__ void bsplit(float x, unsigned short& h, unsigned short& l){
    __nv_bfloat16 hb = __float2bfloat16(x);
    __nv_bfloat16 lb = __float2bfloat16(x - __bfloat162float(hb));
    h = __bfloat16_as_ushort(hb);
    l = __bfloat16_as_ushort(lb);
}
__device__ __forceinline__ void spstore(__nv_bfloat16* hi, __nv_bfloat16* lo, size_t idx, float v){
    unsigned short h,l; bsplit(v,h,l);
    hi[idx]=__ushort_as_bfloat16(h); lo[idx]=__ushort_as_bfloat16(l);
}

#define LDM4(r, addr) \
    asm volatile("ldmatrix.sync.aligned.m8n8.x4.shared.b16 {%0,%1,%2,%3}, [%4];" \
        : "=r"((r)[0]), "=r"((r)[1]), "=r"((r)[2]), "=r"((r)[3]) : "r"(addr))

#define MMA16816(c, a, b0, b1) \
    asm volatile("mma.sync.aligned.m16n8k16.row.col.f32.bf16.bf16.f32 " \
        "{%0,%1,%2,%3},{%4,%5,%6,%7},{%8,%9},{%0,%1,%2,%3};" \
        : "+f"((c)[0]), "+f"((c)[1]), "+f"((c)[2]), "+f"((c)[3]) \
        : "r"((a)[0]), "r"((a)[1]), "r"((a)[2]), "r"((a)[3]), "r"(b0), "r"(b1))

__global__ void init_k(){
    int i=threadIdx.x;
    if(i<8) g_acc[i]=0.0;
    if(i<32){ g_piw[i]=0.0; g_k[i]=0.0; g_mn[i]=0xffffffffu; g_mx[i]=0u; }
}

// ---------------- input splits ----------------
__global__ void xsplit_k(const float* __restrict__ x, __nv_bfloat16* __restrict__ XSp){
    int total = B_*N_*D_;
    for (int idx = blockIdx.x*blockDim.x + threadIdx.x; idx < total; idx += gridDim.x*blockDim.x){
        int b = idx/160, rem = idx - b*160;
        int z = rem>>5, k = rem&31;
        size_t o = (size_t)z*B_*32 + b*32 + k;
        spstore(XSp, XSp + (size_t)N_*B_*32, o, x[idx]);
    }
}
__global__ void hsplit_k(const float* __restrict__ hist, __nv_bfloat16* __restrict__ HSp){
    int total = 2*BH;
    for (int idx = blockIdx.x*blockDim.x + threadIdx.x; idx < total; idx += gridDim.x*blockDim.x){
        int l = idx/BH, rem = idx - l*BH;
        spstore(HSp + (size_t)l*2*BH, HSp + (size_t)l*2*BH + BH, rem, hist[idx]);
    }
}

// ---------------- merged weight prep (single launch; layouts identical to R12) ----------------
struct PrepD {
    const float* W;
    int ldw, wstride, Kreal, NB, KPR, zc, nk;
    long long imgoff;
};
struct PrepAll { PrepD d[11]; };

__global__ void prep_all_k(PrepAll pa, __nv_bfloat16* __restrict__ img){
    const PrepD d = pa.d[blockIdx.x];
    int per = d.NB*d.Kreal;
    int total = d.zc*per;
    int nch = d.NB>>6;
    for (int i = blockIdx.y*blockDim.x + threadIdx.x; i < total; i += gridDim.y*blockDim.x){
        int z2 = i/per, rem = i - z2*per;
        int k,n;
        if (d.nk){ n = rem/d.Kreal; k = rem - n*d.Kreal; }
        else     { k = rem/d.NB;    n = rem - k*d.NB; }
        float v = d.W[(size_t)z2*d.wstride + (d.nk ? (size_t)n*d.ldw + k : (size_t)k*d.ldw + n)];
        unsigned short h,l; bsplit(v,h,l);
        int ch = n>>6, nl = n&63;
        size_t off = (size_t)d.imgoff + ((size_t)z2*nch + ch)*(2*64*d.KPR) + (size_t)nl*d.KPR + k;
        img[off] = __ushort_as_bfloat16(h);
        img[off + 64*d.KPR] = __ushort_as_bfloat16(l);
    }
}

// ---------------- bf16x3 GEMM: A resident in smem, loop over 64-col B chunks ----------------
#define EPI_NONE 0
#define EPI_RELU 1
#define EPI_MISH 2
#define EPI_SIGKL 3
#define EPI_LZ 4

// grid (1, rows/128, z); nch = number of 64-col chunks (total N = 64*nch).
template<int KK, int EPI, int OS>
__global__ __launch_bounds__(256)
void gemm_mm(const __nv_bfloat16* __restrict__ Ah, int lda, int azs, int asplen,
             const __nv_bfloat16* __restrict__ img, int nch,
             const float* __restrict__ bias, int biaszs,
             void* __restrict__ Cv, int ldc, int czs, int csplen,
             const float* __restrict__ aux, int aldc)
{
    constexpr int KPR = KK + 8;
    constexpr int APL = 128*KPR*2;
    constexpr int BPL = 64*KPR*2;
    constexpr int MT = 2;

    extern __shared__ __align__(16) char smem[];
    char* sAh = smem;
    char* sBh = smem + 2*APL;
    double* red = (double*)(smem + 2*APL + 2*BPL);

    int tid = threadIdx.x, wid = tid>>5, lane = tid&31;
    int z = blockIdx.z;
    bias += (size_t)z*biaszs;
    int row0 = blockIdx.y*128;

    float* Cf = nullptr; __nv_bfloat16* Csp = nullptr;
    if (OS==0 && EPI<EPI_SIGKL) Cf  = (float*)Cv + (size_t)z*czs;
    if (OS==1)                  Csp = (__nv_bfloat16*)Cv + (size_t)z*czs;

    // ---- copy A tile (pre-split) once ----
    {
        const __nv_bfloat16* Abase = Ah + (size_t)z*azs + (size_t)row0*lda;
        constexpr int CHk = KK/8;
        constexpr int TOT = 128*CHk*2;
        #pragma unroll
        for (int i=0;i<TOT/256;i++){
            int idx=i*256+tid;
            int p = idx/(128*CHk); int rem = idx - p*(128*CHk);
            int row = rem/CHk, ck = rem - row*CHk;
            uint4 v = *reinterpret_cast<const uint4*>(Abase + (size_t)p*asplen + (size_t)row*lda + ck*8);
            *reinterpret_cast<uint4*>(sAh + (size_t)p*APL + row*KPR*2 + ck*16) = v;
        }
    }

    int wm = wid & 3, wn = wid >> 2;
    int m_base = wm*32, n_base = wn*32;
    int lr = lane & 15, lc = lane >> 4;
    int rsel = lane>>2, csel = (lane&3)*2;

    uint32_t abase = smem_u32(sAh);
    uint32_t bbase = smem_u32(sBh);
    uint32_t arow[MT], brow[2];
    #pragma unroll
    for (int mt=0; mt<MT; mt++) arow[mt] = abase + ((m_base + mt*16 + lr)*KPR)*2 + lc*16;
    #pragma unroll
    for (int g=0; g<2; g++)     brow[g] = bbase + ((n_base + g*16 + lr)*KPR)*2 + lc*16;

    double part = 0.0;

    for (int ch=0; ch<nch; ch++){
        __syncthreads();   // prior chunk's compute done (and A ready on ch=0)
        // ---- load B chunk ----
        {
            const float4* src = reinterpret_cast<const float4*>(img + ((size_t)z*nch + ch)*(2*64*KPR));
            float4* dst = reinterpret_cast<float4*>(sBh);
            constexpr int CNT = 2*BPL/16;
            for (int i=tid; i<CNT; i+=256) dst[i] = src[i];
        }
        __syncthreads();

        float c[MT][4][4];
        #pragma unroll
        for(int mt=0;mt<MT;mt++)
            #pragma unroll
            for(int nt=0;nt<4;nt++)
                #pragma unroll
                for(int q=0;q<4;q++) c[mt][nt][q]=0.f;

        for (int ks=0; ks<KK/16; ks++){
            uint32_t koff = ks*32;
            uint32_t ah[MT][4], al[MT][4];
            #pragma unroll
            for (int mt=0; mt<MT; mt++){
                LDM4(ah[mt], arow[mt] + koff);
                LDM4(al[mt], arow[mt] + koff + APL);
            }
            uint32_t bh0[4],bh1[4],bl0[4],bl1[4];
            #pragma unroll
            for (int g=0; g<2; g++){
                uint32_t r[4];
                LDM4(r, brow[g] + koff);
                bh0[2*g]=r[0]; bh0[2*g+1]=r[1]; bh1[2*g]=r[2]; bh1[2*g+1]=r[3];
                LDM4(r, brow[g] + koff + BPL);
                bl0[2*g]=r[0]; bl0[2*g+1]=r[1]; bl1[2*g]=r[2]; bl1[2*g+1]=r[3];
            }
            #pragma unroll
            for (int mt=0; mt<MT; mt++){
                #pragma unroll
                for (int nt=0; nt<4; nt++){
                    MMA16816(c[mt][nt], ah[mt], bh0[nt], bh1[nt]);
                    MMA16816(c[mt][nt], ah[mt], bl0[nt], bl1[nt]);
                    MMA16816(c[mt][nt], al[mt], bh0[nt], bh1[nt]);
                }
            }
        }

        // ---- per-chunk epilogue ----
        int col0 = ch*64;
        #pragma unroll
        for (int mt=0; mt<MT; mt++){
            int rloc = m_base + mt*16 + rsel;
            #pragma unroll
            for (int nt=0; nt<4; nt++){
                int cg = col0 + n_base + nt*8 + csel;
                float b0 = bias[cg];
                float b1 = bias[cg+1];
                #pragma unroll
                for (int half=0; half<2; half++){
                    int row = row0 + rloc + half*8;
                    float v0 = c[mt][nt][half*2+0] + b0;
                    float v1 = c[mt][nt][half*2+1] + b1;
                    if (EPI==EPI_SIGKL || EPI==EPI_LZ){
                        const float* ap = &aux[(size_t)row*aldc + cg];
                        float m0 = ap[0], m1 = ap[1];
                        if (EPI==EPI_SIGKL){
                            float sp0 = softplusf(v0), sp1 = softplusf(v1);
                            float va0 = sp0*sp0, va1 = sp1*sp1;
                            part += (double)(0.5f*(m0*m0 + va0 - logf(va0+1e-8f) - 1.0f));
                            part += (double)(0.5f*(m1*m1 + va1 - logf(va1+1e-8f) - 1.0f));
                        } else {
                            float d0 = m0-v0, d1 = m1-v1;
                            part += (double)(d0*d0) + (double)(d1*d1);
                        }
                    } else {
                        if (EPI==EPI_RELU){ v0=fmaxf(v0,0.f); v1=fmaxf(v1,0.f); }
                        else if (EPI==EPI_MISH){ v0=mishf(v0); v1=mishf(v1); }
                        size_t o = (size_t)row*ldc + cg;
                        if (OS==0){
                            float2 ov; ov.x=v0; ov.y=v1;
                            *reinterpret_cast<float2*>(&Cf[o]) = ov;
                        } else {
                            unsigned short h0,l0,h1,l1; bsplit(v0,h0,l0); bsplit(v1,h1,l1);
                            *reinterpret_cast<uint32_t*>(&Csp[o]) = (unsigned)h0 | ((unsigned)h1<<16);
                            *reinterpret_cast<uint32_t*>(&Csp[o+csplen]) = (unsigned)l0 | ((unsigned)l1<<16);
                        }
                    }
                }
            }
        }
    }

    if (EPI==EPI_SIGKL || EPI==EPI_LZ){
        #pragma unroll
        for (int o=16;o;o>>=1) part += __shfl_xor_sync(0xffffffffu, part, o);
        __syncthreads();
        if (lane==0) red[wid]=part;
        __syncthreads();
        if (tid==0){
            double s=0; for(int w=0;w<8;w++) s+=red[w];
            atomicAdd(&g_acc[EPI==EPI_SIGKL?0:4], s);
        }
    }
}

// ---------------- elementwise kernels ----------------
__global__ void agg_k(const float* __restrict__ g, const float* __restrict__ ew,
                      __nv_bfloat16* __restrict__ S){
    int idx = blockIdx.x*256+threadIdx.x;
    int b=idx>>7, h=idx&127;
    const float* gb = g + (size_t)b*640 + h;
    float g0=gb[0],g1=gb[128],g2=gb[256],g3=gb[384],g4=gb[512];
    const float* e = ew + (size_t)b*10;
    float o0 = g0;
    float o1 = g1 + e[0]*g0;
    float o2 = g2 + e[1]*g0 + e[4]*g1;
    float o3 = g3 + e[2]*g0 + e[5]*g1 + e[7]*g2;
    float o4 = g4 + e[3]*g0 + e[6]*g1 + e[8]*g2 + e[9]*g3;
    __nv_bfloat16* lo = S + SPLROW;
    size_t base = (size_t)b*640 + h;
    spstore(S,lo,base,      o0);
    spstore(S,lo,base+128,  o1);
    spstore(S,lo,base+256,  o2);
    spstore(S,lo,base+384,  o3);
    spstore(S,lo,base+512,  o4);
}

__global__ void gf_k(const float* __restrict__ m, __nv_bfloat16* __restrict__ G){
    int idx = blockIdx.x*256+threadIdx.x;
    int b=idx>>7, h=idx&127;
    const float* mb = m + (size_t)b*640 + h;
    spstore(G, G + (size_t)B_*H_, idx, (mb[0]+mb[128]+mb[256]+mb[384]+mb[512])*0.2f);
}

__global__ void cell_k(const float* __restrict__ gi, const float* __restrict__ gh,
                       const float* __restrict__ hprev, float* __restrict__ hout,
                       __nv_bfloat16* __restrict__ cs){
    int idx = blockIdx.x*256+threadIdx.x;
    int b=idx>>7, h=idx&127;
    int base = b*384 + h;
    float r = sigmf(gi[base]     + gh[base]);
    float z = sigmf(gi[base+128] + gh[base+128]);
    float n = tanhf(gi[base+256] + r*gh[base+256]);
    float v = (1.f-z)*n + z*hprev[idx];
    hout[idx] = v;
    if (cs) spstore(cs, cs + (size_t)B_*H_, idx, v);
}

__global__ void causal_k(const float* __restrict__ m, const float* __restrict__ ew,
                         const float* __restrict__ cm, float* __restrict__ czf,
                         __nv_bfloat16* __restrict__ CZ, __nv_bfloat16* __restrict__ PS){
    int idx = blockIdx.x*256+threadIdx.x;
    int b=idx>>7, h=idx&127;
    const float* mb = m + (size_t)b*640 + h;
    const float* e  = ew + (size_t)b*10;
    float c01=cm[1]*e[0],  c02=cm[2]*e[1],  c03=cm[3]*e[2],  c04=cm[4]*e[3];
    float c12=cm[7]*e[4],  c13=cm[8]*e[5],  c14=cm[9]*e[6];
    float c23=cm[13]*e[7], c24=cm[14]*e[8];
    float c34=cm[19]*e[9];
    float z0=mb[0];
    float z1=mb[128]+c01*z0;
    float z2=mb[256]+c02*z0+c12*z1;
    float z3=mb[384]+c03*z0+c13*z1+c23*z2;
    float z4=mb[512]+c04*z0+c14*z1+c24*z2+c34*z3;
    size_t base = (size_t)b*640 + h;
    float* czb = czf + base;
    czb[0]=z0; czb[128]=z1; czb[256]=z2; czb[384]=z3; czb[512]=z4;
    __nv_bfloat16* czlo = CZ + SPLROW;
    spstore(CZ,czlo,base,z0); spstore(CZ,czlo,base+128,z1); spstore(CZ,czlo,base+256,z2);
    spstore(CZ,czlo,base+384,z3); spstore(CZ,czlo,base+512,z4);
    float zv[5]={z0,z1,z2,z3,z4};
    __nv_bfloat16* pslo = PS + SPLROW;
    #pragma unroll
    for(int j=0;j<5;j++){
        float s=0.f;
        #pragma unroll
        for(int i=0;i<5;i++){
            if (cm[i*5+j]!=0.f) s += zv[i];
        }
        spstore(PS,pslo,base + (size_t)j*128, s);
    }
}

__global__ __launch_bounds__(256)
void loss_k(const float* __restrict__ dec, const float* __restrict__ ytp, float* __restrict__ out){
    int warp = threadIdx.x>>5, lane = threadIdx.x&31;
    int base = blockIdx.x*128;
    const float ZA = 1.959963984540054f;
    double ll_s=0.0, piw_s=0.0;
    float reg_s=0.f, cls_s=0.f;
    int k_s=0;
    float mn=3e38f, mx=-3e38f;
    for(int t=0;t<16;t++){
        int row = base + warp*16 + t;
        int n = row % 5;
        const float* dr = dec + (size_t)row*64;
        float mean = dr[lane];
        float var  = expf(dr[32+lane]);
        size_t oi = (size_t)row*32 + lane;
        out[oi]=mean; out[OFF_VAR+oi]=var;
        float yt = ytp[oi];
        float vs = var+1e-6f;
        float dm = yt-mean;
        ll_s += (double)(-0.5f*(dm*dm/vs + logf(6.283185307179586f*vs)));
        float d2 = dm*dm;
        float ssum=d2;
        #pragma unroll
        for(int o=16;o;o>>=1) ssum += __shfl_xor_sync(0xffffffffu,ssum,o);
        if (lane==0 && n<4) reg_s += ssum*(1.f/32.f);
        if (n==4){
            float bce = fmaxf(mean,0.f)-mean*yt+log1pf(expf(-fabsf(mean)));
            float bs=bce;
            #pragma unroll
            for(int o=16;o;o>>=1) bs += __shfl_xor_sync(0xffffffffu,bs,o);
            if (lane==0) cls_s += bs*(1.f/32.f);
        }
        float s = sqrtf(var+1e-6f);
        float lo = mean-ZA*s, up = mean+ZA*s;
        if (yt>=lo && yt<=up){ piw_s += (double)(up-lo); k_s++; }
        mn=fminf(mn,yt); mx=fmaxf(mx,yt);
    }
    #pragma unroll
    for(int o=16;o;o>>=1) ll_s += __shfl_xor_sync(0xffffffffu,ll_s,o);

    __shared__ double sll[8];
    __shared__ float sreg[8], scls[8];
    __shared__ float spiw[8][32], sk[8][32];
    __shared__ unsigned smn[8][32], smx[8][32];
    if (lane==0){ sll[warp]=ll_s; sreg[warp]=reg_s; scls[warp]=cls_s; }
    spiw[warp][lane]=(float)piw_s; sk[warp][lane]=(float)k_s;
    smn[warp][lane]=fenc(mn); smx[warp][lane]=fenc(mx);
    __syncthreads();
    if (warp==0){
        double psum=0, ksum=0; unsigned mnu=0xffffffffu, mxu=0u;
        for(int w=0;w<8;w++){
            psum+=(double)spiw[w][lane]; ksum+=(double)sk[w][lane];
            mnu=min(mnu,smn[w][lane]); mxu=max(mxu,smx[w][lane]);
        }
        atomicAdd(&g_piw[lane],psum); atomicAdd(&g_k[lane],ksum);
        atomicMin(&g_mn[lane],mnu);   atomicMax(&g_mx[lane],mxu);
        if (lane==0){
            double L=0; float R=0,Cc=0;
            for(int w=0;w<8;w++){ L+=sll[w]; R+=sreg[w]; Cc+=scls[w]; }
            atomicAdd(&g_acc[1],L); atomicAdd(&g_acc[2],(double)R); atomicAdd(&g_acc[3],(double)Cc);
        }
    }
}

__global__ void fin_k(float* __restrict__ out){
    int lane=threadIdx.x;
    double t=0.0, kc=0.0;
    double p=g_piw[lane]; kc=g_k[lane];
    float ymn=fdec(g_mn[lane]), ymx=fdec(g_mx[lane]);
    t = p/(kc+1e-6)/((double)(ymx-ymn)+1e-6);
    #pragma unroll
    for(int o=16;o;o>>=1){
        t  += __shfl_xor_sync(0xffffffffu,t,o);
        kc += __shfl_xor_sync(0xffffffffu,kc,o);
    }
    if (lane==0){
        float pinaw=(float)(t/32.0);
        float picp =(float)(kc/5242880.0);
        float kl   =(float)g_acc[0];
        float elbo = kl/32768.0f - (float)(g_acc[1]/5242880.0);
        float l_reg=(float)(g_acc[2]/(4.0*32768.0+1e-6));
        float l_cls=(float)(g_acc[3]/(32768.0+1e-6));
        float l_rec=l_reg+l_cls;
        float l_pi = pinaw - sqrtf(5.f)*picp;
        float l_z  =(float)(g_acc[4]/(163840.0*128.0));
        float dag  = 0.f;  // trace((I+ac)^5) == N exactly (strictly upper triangular)
        float total= powf(elbo*l_rec*l_pi*l_z*(dag+1e-6f), 0.2f);
        out[OFF_TOT]=total;
        out[OFF_LS+0]=elbo; out[OFF_LS+1]=l_rec; out[OFF_LS+2]=l_pi;
        out[OFF_LS+3]=l_z;  out[OFF_LS+4]=dag;
    }
}

// ---------------- launcher ----------------
static inline int smsz(int KK){
    int KPR = KK+8;
    return 2*(128*KPR*2) + 2*(64*KPR*2) + 64;
}

extern "C" void kernel_launch(void* const* d_in, const int* in_sizes, int n_in,
                              void* d_out, int out_size)
{
    const float* x    =(const float*)d_in[0];
    const float* ytr  =(const float*)d_in[1];
    const float* ew   =(const float*)d_in[2];
    const float* hist =(const float*)d_in[3];
    const float* eW1  =(const float*)d_in[4];
    const float* eb1  =(const float*)d_in[5];
    const float* eW2  =(const float*)d_in[6];
    const float* eb2  =(const float*)d_in[7];
    const float* gW   =(const float*)d_in[8];
    const float* gb   =(const float*)d_in[9];
    const float* muW  =(const float*)d_in[10];
    const float* mub  =(const float*)d_in[11];
    const float* sgW  =(const float*)d_in[12];
    const float* sgb  =(const float*)d_in[13];
    const float* Wih  =(const float*)d_in[14];
    const float* Whh  =(const float*)d_in[15];
    const float* bih  =(const float*)d_in[16];
    const float* bhh  =(const float*)d_in[17];
    const float* cm   =(const float*)d_in[18];
    const float* cW1  =(const float*)d_in[19];
    const float* cb1  =(const float*)d_in[20];
    const float* cW2  =(const float*)d_in[21];
    const float* cb2  =(const float*)d_in[22];
    const float* dW1  =(const float*)d_in[23];
    const float* db1  =(const float*)d_in[24];
    const float* dW2  =(const float*)d_in[25];
    const float* db2  =(const float*)d_in[26];
    float* out=(float*)d_out;

    float *pBA,*pBB,*pBD,*pDEC,*pGI,*pGH;
    __nv_bfloat16 *pW,*pS0,*pS1,*pS2,*pXS,*pHS,*pGFS,*pCS;
    cudaGetSymbolAddress((void**)&pBA,BA);
    cudaGetSymbolAddress((void**)&pBB,BB);
    cudaGetSymbolAddress((void**)&pBD,BD);
    cudaGetSymbolAddress((void**)&pDEC,DEC);
    cudaGetSymbolAddress((void**)&pGI,GI);
    cudaGetSymbolAddress((void**)&pGH,GH);
    cudaGetSymbolAddress((void**)&pW,WIMG);
    cudaGetSymbolAddress((void**)&pS0,S0);
    cudaGetSymbolAddress((void**)&pS1,S1);
    cudaGetSymbolAddress((void**)&pS2,S2);
    cudaGetSymbolAddress((void**)&pXS,XS);
    cudaGetSymbolAddress((void**)&pHS,HS);
    cudaGetSymbolAddress((void**)&pGFS,GFS);
    cudaGetSymbolAddress((void**)&pCS,CS);

    const int SM_MAIN = smsz(128);
    const int SM_ENC1 = smsz(32);
    cudaFuncSetAttribute(gemm_mm<128,EPI_NONE,0>,  cudaFuncAttributeMaxDynamicSharedMemorySize, SM_MAIN);
    cudaFuncSetAttribute(gemm_mm<128,EPI_RELU,0>,  cudaFuncAttributeMaxDynamicSharedMemorySize, SM_MAIN);
    cudaFuncSetAttribute(gemm_mm<128,EPI_RELU,1>,  cudaFuncAttributeMaxDynamicSharedMemorySize, SM_MAIN);
    cudaFuncSetAttribute(gemm_mm<128,EPI_MISH,1>,  cudaFuncAttributeMaxDynamicSharedMemorySize, SM_MAIN);
    cudaFuncSetAttribute(gemm_mm<128,EPI_SIGKL,0>, cudaFuncAttributeMaxDynamicSharedMemorySize, SM_MAIN);
    cudaFuncSetAttribute(gemm_mm<128,EPI_LZ,0>,    cudaFuncAttributeMaxDynamicSharedMemorySize, SM_MAIN);
    cudaFuncSetAttribute(gemm_mm<32,EPI_RELU,1>,   cudaFuncAttributeMaxDynamicSharedMemorySize, SM_ENC1);

    // merged prep descriptor table (image layout identical to R12)
    PrepAll pa;
    auto setd=[&](int i, const float* W, int ldw, int ws, int Kr, int NB, int KPR, int zc, int nk, long long off){
        pa.d[i] = PrepD{W,ldw,ws,Kr,NB,KPR,zc,nk,off};
    };
    setd(0,  eW1, 128, 4096,  32, 128, 40, 5, 0, IMG_ENC1);
    setd(1,  eW2, 128, 16384, 128,128,136, 5, 0, IMG_ENC2);
    setd(2,  gW,  128, 16384, 128,128,136, 2, 0, IMG_GCN);
    setd(3,  muW, 128, 0,     128,128,136, 1, 0, IMG_MU);
    setd(4,  sgW, 128, 0,     128,128,136, 1, 0, IMG_SG);
    setd(5,  Wih, 128, 16384, 128,128,136, 6, 1, IMG_WIH);
    setd(6,  Whh, 128, 16384, 128,128,136, 6, 1, IMG_WHH);
    setd(7,  cW1, 128, 0,     128,128,136, 1, 0, IMG_CM1);
    setd(8,  cW2, 128, 0,     128,128,136, 1, 0, IMG_CM2);
    setd(9,  dW1, 128, 16384, 128,128,136, 5, 0, IMG_DW1);
    setd(10, dW2, 64,  8192,  128, 64,136, 5, 0, IMG_DW2);

    init_k<<<1,64>>>();
    xsplit_k<<<1024,256>>>(x, pXS);
    hsplit_k<<<2048,256>>>(hist, pHS);
    prep_all_k<<<dim3(11,28),256>>>(pa, pW);

    gemm_mm<32,EPI_RELU,1><<<dim3(1,256,5),256,SM_ENC1>>>(
        pXS,32,B_*32,N_*B_*32, pW+IMG_ENC1,2, eb1,128, pS0,128,B_*128,SPLROW, nullptr,0);
    gemm_mm<128,EPI_NONE,0><<<dim3(1,256,5),256,SM_MAIN>>>(
        pS0,128,B_*128,SPLROW, pW+IMG_ENC2,2, eb2,128, pBB,640,128,0, nullptr,0);

    // ---- GCN x2 ----
    agg_k<<<16384,256>>>(pBB, ew, pS1);
    gemm_mm<128,EPI_RELU,0><<<dim3(1,1280,1),256,SM_MAIN>>>(
        pS1,128,0,SPLROW, pW+IMG_GCN,2,         gb,0,     pBA,128,0,0, nullptr,0);
    agg_k<<<16384,256>>>(pBA, ew, pS0);
    gemm_mm<128,EPI_RELU,1><<<dim3(1,1280,1),256,SM_MAIN>>>(
        pS0,128,0,SPLROW, pW+IMG_GCN+2*CH136,2, gb+128,0, pS1,128,0,SPLROW, nullptr,0);

    // ---- mu / sigma(+KL) ----
    gemm_mm<128,EPI_NONE,0><<<dim3(1,1280,1),256,SM_MAIN>>>(
        pS1,128,0,SPLROW, pW+IMG_MU,2, mub,0, pBD,128,0,0, nullptr,0);
    gemm_mm<128,EPI_SIGKL,0><<<dim3(1,1280,1),256,SM_MAIN>>>(
        pS1,128,0,SPLROW, pW+IMG_SG,2, sgb,0, nullptr,0,0,0, pBD,128);

    gf_k<<<16384,256>>>(pBD, pGFS);

    // ---- GRU x2 ----
    const __nv_bfloat16* ginS = pGFS;
    for (int l=0;l<2;l++){
        gemm_mm<128,EPI_NONE,0><<<dim3(1,256,1),256,SM_MAIN>>>(
            ginS,128,0,B_*128, pW+IMG_WIH+(size_t)l*6*CH136,6, bih+l*384,0, pGI,384,0,0, nullptr,0);
        gemm_mm<128,EPI_NONE,0><<<dim3(1,256,1),256,SM_MAIN>>>(
            pHS+(size_t)l*2*BH,128,0,BH, pW+IMG_WHH+(size_t)l*6*CH136,6, bhh+l*384,0, pGH,384,0,0, nullptr,0);
        cell_k<<<16384,256>>>(pGI,pGH, hist+(size_t)l*BH, out+OFF_GRU+(size_t)l*BH,
                              l==0 ? pCS : (__nv_bfloat16*)nullptr);
        ginS = pCS;
    }

    // ---- causal + cm MLP(+l_z) ----
    causal_k<<<16384,256>>>(pBD, ew, cm, pBA, pS0, pS1);
    gemm_mm<128,EPI_MISH,1><<<dim3(1,1280,1),256,SM_MAIN>>>(
        pS1,128,0,SPLROW, pW+IMG_CM1,2, cb1,0, pS2,128,0,SPLROW, nullptr,0);
    gemm_mm<128,EPI_LZ,0><<<dim3(1,1280,1),256,SM_MAIN>>>(
        pS2,128,0,SPLROW, pW+IMG_CM2,2, cb2,0, nullptr,0,0,0, pBA,128);

    // ---- decoder ----
    gemm_mm<128,EPI_MISH,1><<<dim3(1,256,5),256,SM_MAIN>>>(
        pS0,640,128,SPLROW, pW+IMG_DW1,2, db1,128, pS1,128,B_*128,SPLROW, nullptr,0);
    gemm_mm<128,EPI_NONE,0><<<dim3(1,256,5),256,SM_MAIN>>>(
        pS1,128,B_*128,SPLROW, pW+IMG_DW2,1, db2,64, pDEC,320,64,0, nullptr,0);

    // ---- losses ----
    loss_k<<<1280,256>>>(pDEC, ytr, out);
    fin_k<<<1,32>>>(out);
}